// round 6
// baseline (speedup 1.0000x reference)
#include <cuda_runtime.h>
#include <cstdint>

// ---------------- problem constants ----------------
#define NN_MAX 50000
#define E_MAX  400000
#define ET_MAX (E_MAX + NN_MAX)
#define FIN    128
#define D1     512
#define HIDC   64
#define HEADS  8
#define NEG    0.2f

// ---------------- scratch ----------------
__device__ float    g_XA [NN_MAX * (size_t)(HEADS * FIN)];  // [N,8,128] alpha-aggregated x
__device__ float    g_H1A[NN_MAX * (size_t)D1];
__device__ float    g_H2 [NN_MAX * (size_t)HIDC];
__device__ float    g_WT1[D1 * FIN];      // W1^T  [512,128]
__device__ float    g_WT2[HIDC * D1];     // W2^T  [64,512]
__device__ float    g_WA1[FIN * 16];      // x->logits fold: [128][16] (8 src, 8 dst)
__device__ float    g_WA2[D1 * 2];        // h1a->logits fold: [512][2]
__device__ float    g_ALS1[NN_MAX * HEADS];
__device__ float    g_ALD1[NN_MAX * HEADS];
__device__ float    g_ALS2[NN_MAX];
__device__ float    g_ALD2[NN_MAX];
__device__ int      g_SRC[E_MAX];
__device__ int      g_DST[E_MAX];
__device__ int      g_DEG[NN_MAX];
__device__ int      g_ROFF[NN_MAX + 1];
__device__ int      g_CUR[NN_MAX];
__device__ int      g_CSRS[ET_MAX];
__device__ int      g_FLAG64;

// ---------------- helpers ----------------
__device__ __forceinline__ float lrelu(float x) { return x > 0.f ? x : NEG * x; }
__device__ __forceinline__ uint32_t f2tf32(float f) {
    uint32_t r;
    asm("cvt.rna.tf32.f32 %0, %1;" : "=r"(r) : "f"(f));
    return r;
}
__device__ __forceinline__ void mma_tf32(float* c, const uint32_t* a, const uint32_t* b) {
    asm volatile("mma.sync.aligned.m16n8k8.row.col.f32.tf32.tf32.f32 "
        "{%0,%1,%2,%3}, {%4,%5,%6,%7}, {%8,%9}, {%0,%1,%2,%3};"
        : "+f"(c[0]), "+f"(c[1]), "+f"(c[2]), "+f"(c[3])
        : "r"(a[0]), "r"(a[1]), "r"(a[2]), "r"(a[3]), "r"(b[0]), "r"(b[1]));
}

// ---------------- edge dtype detection + conversion ----------------
__global__ void k_detect(const int* __restrict__ p, int E) {
    __shared__ int nz;
    if (threadIdx.x == 0) nz = 0;
    __syncthreads();
    int total = 2 * E; if (total > 4096) total = 4096;
    int local = 0;
    for (int i = 2 * (int)threadIdx.x + 1; i < total; i += 2 * (int)blockDim.x)
        local |= p[i];
    if (local) atomicOr(&nz, 1);
    __syncthreads();
    if (threadIdx.x == 0) g_FLAG64 = (nz == 0) ? 1 : 0;
}
__global__ void k_convert(const void* __restrict__ buf, int E) {
    int i = blockIdx.x * blockDim.x + threadIdx.x;
    if (i >= E) return;
    if (g_FLAG64) {
        const long long* p = (const long long*)buf;
        g_SRC[i] = (int)p[i];
        g_DST[i] = (int)p[E + i];
    } else {
        const int* p = (const int*)buf;
        g_SRC[i] = p[i];
        g_DST[i] = p[E + i];
    }
}

// ---------------- CSR build ----------------
__global__ void k_zero_deg(int n) {
    int i = blockIdx.x * blockDim.x + threadIdx.x;
    if (i < n) g_DEG[i] = 0;
}
__global__ void k_degree(int E, int Et) {
    int i = blockIdx.x * blockDim.x + threadIdx.x;
    if (i >= Et) return;
    int d = (i < E) ? g_DST[i] : (i - E);
    atomicAdd(&g_DEG[d], 1);
}
__global__ void k_scan(int NN) {
    __shared__ int sums[1024];
    int t = threadIdx.x;
    int chunk = (NN + 1023) >> 10;
    int beg = t * chunk;
    int end = beg + chunk; if (end > NN) end = NN;
    int s = 0;
    for (int i = beg; i < end; i++) s += g_DEG[i];
    sums[t] = s;
    __syncthreads();
    for (int off = 1; off < 1024; off <<= 1) {
        int v = (t >= off) ? sums[t - off] : 0;
        __syncthreads();
        sums[t] += v;
        __syncthreads();
    }
    int run = (t == 0) ? 0 : sums[t - 1];
    for (int i = beg; i < end; i++) {
        int d = g_DEG[i];
        g_ROFF[i] = run;
        g_CUR[i]  = run;
        run += d;
    }
    if (t == 0) g_ROFF[NN] = sums[1023];
}
__global__ void k_scatter(int E, int Et) {
    int i = blockIdx.x * blockDim.x + threadIdx.x;
    if (i >= Et) return;
    int s, d;
    if (i < E) { s = g_SRC[i]; d = g_DST[i]; }
    else       { s = d = i - E; }
    int pos = atomicAdd(&g_CUR[d], 1);
    g_CSRS[pos] = s;
}

// ---------------- weight transposes ----------------
__global__ void k_transpose(const float* __restrict__ W, float* __restrict__ WT, int K, int N) {
    __shared__ float tile[32][33];
    int n0 = blockIdx.x * 32, k0 = blockIdx.y * 32;
    int tx = threadIdx.x, ty = threadIdx.y;   // 32 x 8
#pragma unroll
    for (int i = 0; i < 32; i += 8)
        tile[ty + i][tx] = W[(size_t)(k0 + ty + i) * N + n0 + tx];
    __syncthreads();
#pragma unroll
    for (int i = 0; i < 32; i += 8)
        WT[(size_t)(n0 + ty + i) * K + k0 + tx] = tile[tx][ty + i];
}

// ---------------- fold attention vectors into weights ----------------
// WA1[f][c] = sum_j W1[f, h*64+j] * a1{src|dst}[h*64+j],  c = h (src) / 8+h (dst)
// WA2[f][c] = sum_j W2[f, j] * a2{src|dst}[j]
__global__ __launch_bounds__(32) void k_wa(
    const float* __restrict__ W1, const float* __restrict__ as1, const float* __restrict__ ad1,
    const float* __restrict__ W2, const float* __restrict__ as2, const float* __restrict__ ad2)
{
    int idx = blockIdx.x;
    int t = threadIdx.x;
    const float *wrow, *av;
    float* outp;
    if (idx < FIN * 16) {
        int f = idx >> 4, c = idx & 15, h = c & 7;
        wrow = W1 + (size_t)f * D1 + h * 64;
        av   = ((c < 8) ? as1 : ad1) + h * 64;
        outp = g_WA1 + f * 16 + c;
    } else {
        int i2 = idx - FIN * 16;
        int f = i2 >> 1, c = i2 & 1;
        wrow = W2 + (size_t)f * HIDC;
        av   = c ? ad2 : as2;
        outp = g_WA2 + f * 2 + c;
    }
    float p = wrow[t] * av[t] + wrow[t + 32] * av[t + 32];
#pragma unroll
    for (int o = 16; o; o >>= 1) p += __shfl_xor_sync(0xffffffffu, p, o);
    if (t == 0) *outp = p;
}

// ---------------- exact fp32 logits: AL1 = x @ WA1 ----------------
__global__ __launch_bounds__(256) void k_al1(const float* __restrict__ x, int NN) {
    __shared__ float s_w[16][128];   // transposed WA1 for conflict-free reads
    int t = threadIdx.x;
    for (int i = t; i < 2048; i += 256) s_w[i & 15][i >> 4] = g_WA1[i];
    __syncthreads();
    int w = t >> 5, l = t & 31;
    int n = blockIdx.x * 8 + w;
    if (n >= NN) return;
    float xv[4];
#pragma unroll
    for (int k = 0; k < 4; k++) xv[k] = x[(size_t)n * FIN + l + 32 * k];
    float r[16];
#pragma unroll
    for (int c = 0; c < 16; c++) {
        float p = 0.f;
#pragma unroll
        for (int k = 0; k < 4; k++) p += xv[k] * s_w[c][l + 32 * k];
#pragma unroll
        for (int o = 16; o; o >>= 1) p += __shfl_xor_sync(0xffffffffu, p, o);
        r[c] = p;
    }
    if (l == 0) {
#pragma unroll
        for (int h = 0; h < 8; h++) {
            g_ALS1[n * HEADS + h] = r[h];
            g_ALD1[n * HEADS + h] = r[8 + h];
        }
    }
}

// ---------------- layer 1: fused softmax stats + aggregate x -> XA ----------------
__global__ __launch_bounds__(256) void k_gat1(const float* __restrict__ x, int NN) {
    __shared__ float  s_red[256];
    __shared__ float  s_max[8], s_inv[8];
    __shared__ float  s_alpha[8][8];
    __shared__ int    s_sidx[8];
    __shared__ float4 sx[8][32];
    int n = blockIdx.x;
    int t = threadIdx.x;
    int h = t & 7, el = t >> 3;
    float ald = g_ALD1[n * HEADS + h];
    int j0 = g_ROFF[n], j1 = g_ROFF[n + 1];

    // pass A: per-head max
    float mx = -1e30f;
    for (int j = j0 + el; j < j1; j += 32) {
        int s = g_CSRS[j];
        mx = fmaxf(mx, lrelu(g_ALS1[s * HEADS + h] + ald));
    }
    s_red[el * 8 + h] = mx;
    __syncthreads();
#pragma unroll
    for (int off = 128; off >= 8; off >>= 1) {
        if (t < off) s_red[t] = fmaxf(s_red[t], s_red[t + off]);
        __syncthreads();
    }
    if (t < 8) s_max[t] = s_red[t];
    __syncthreads();

    // pass B: per-head denom
    float sm = 0.f;
    for (int j = j0 + el; j < j1; j += 32) {
        int s = g_CSRS[j];
        sm += __expf(lrelu(g_ALS1[s * HEADS + h] + ald) - s_max[h]);
    }
    s_red[el * 8 + h] = sm;
    __syncthreads();
#pragma unroll
    for (int off = 128; off >= 8; off >>= 1) {
        if (t < off) s_red[t] += s_red[t + off];
        __syncthreads();
    }
    if (t < 8) s_inv[t] = 1.f / s_red[t];
    __syncthreads();

    // pass C: weighted aggregate of x rows
    int hh = t >> 5, f4 = t & 31;
    float4 acc = make_float4(0.f, 0.f, 0.f, 0.f);
    const float4* x4 = (const float4*)x;
    for (int jb = j0; jb < j1; jb += 8) {
        int cnt = j1 - jb; if (cnt > 8) cnt = 8;
        if (t < cnt) s_sidx[t] = g_CSRS[jb + t];
        __syncthreads();
        if (t < 64) {
            int q = t >> 3, ch = t & 7;
            if (q < cnt) {
                int s = s_sidx[q];
                float e = lrelu(g_ALS1[s * HEADS + ch] + ald);
                s_alpha[q][ch] = __expf(e - s_max[ch]) * s_inv[ch];
            }
        }
        {
            int q2 = t >> 5;
            if (q2 < cnt) sx[q2][f4] = x4[(size_t)s_sidx[q2] * 32 + f4];
        }
        __syncthreads();
        for (int q = 0; q < cnt; q++) {
            float a = s_alpha[q][hh];
            float4 v = sx[q][f4];
            acc.x += a * v.x; acc.y += a * v.y; acc.z += a * v.z; acc.w += a * v.w;
        }
        __syncthreads();
    }
    ((float4*)g_XA)[(size_t)n * 256 + hh * 32 + f4] = acc;
}

// ================= layer-1 GEMM: H1A = relu(XA @ W1 + b1), fused AL2 =================
// per CTA: 128 rows, loop 8 heads (XA[:,h,:] [128x128] @ W1h [128x64]).
// epilogue computes AL2 = H1A @ WA2 in fp32 (exact given H1A).
#define H1_AS   0        // uint32 [128*36]
#define H1_BS   4608     // uint32 [64*36]
#define H1_BUF  6912     // float  [128*33]
#define H1_WA2  11136    // float  [1024]
#define H1_B1   12160    // float  [512]
#define H1_ALS  12672    // float  [128]
#define H1_ALD  12800    // float  [128]
#define H1_SMEMF 12928
#define H1_SMEMB (H1_SMEMF * 4)

__global__ __launch_bounds__(256)
void k_h1gemm(const float* __restrict__ b1, int M)
{
    extern __shared__ float sm[];
    uint32_t* As = (uint32_t*)(sm + H1_AS);
    uint32_t* Bs = (uint32_t*)(sm + H1_BS);
    float* buf   = sm + H1_BUF;
    float* s_wa2 = sm + H1_WA2;
    float* s_b1  = sm + H1_B1;
    float* s_als = sm + H1_ALS;
    float* s_ald = sm + H1_ALD;

    int tid = threadIdx.x;
    int wid = tid >> 5, lane = tid & 31;
    int wm = wid >> 1, wn = wid & 1;
    int m0 = blockIdx.x * 128;

    for (int i = tid; i < 1024; i += 256) s_wa2[i] = g_WA2[i];
    for (int i = tid; i < 512; i += 256)  s_b1[i]  = b1[i];
    if (tid < 128) { s_als[tid] = 0.f; s_ald[tid] = 0.f; }

    for (int h = 0; h < HEADS; h++) {
        float acc[2][4][4];
#pragma unroll
        for (int i = 0; i < 2; i++)
#pragma unroll
            for (int j = 0; j < 4; j++)
#pragma unroll
                for (int k = 0; k < 4; k++) acc[i][j][k] = 0.f;

        for (int k0 = 0; k0 < FIN; k0 += 32) {
            __syncthreads();
#pragma unroll
            for (int it = 0; it < 4; it++) {
                int idx = tid + it * 256;
                int row = idx >> 3, c4 = (idx & 7) * 4;
                int m = m0 + row; if (m >= M) m = M - 1;
                float4 v = *(const float4*)(g_XA + (size_t)m * 1024 + h * 128 + k0 + c4);
                uint32_t* p = As + row * 36 + c4;
                p[0] = f2tf32(v.x); p[1] = f2tf32(v.y); p[2] = f2tf32(v.z); p[3] = f2tf32(v.w);
            }
#pragma unroll
            for (int it = 0; it < 2; it++) {
                int idx = tid + it * 256;
                int row = idx >> 3, c4 = (idx & 7) * 4;
                float4 v = *(const float4*)(g_WT1 + (size_t)(h * 64 + row) * FIN + k0 + c4);
                uint32_t* p = Bs + row * 36 + c4;
                p[0] = f2tf32(v.x); p[1] = f2tf32(v.y); p[2] = f2tf32(v.z); p[3] = f2tf32(v.w);
            }
            __syncthreads();
#pragma unroll
            for (int kk = 0; kk < 32; kk += 8) {
                uint32_t a[2][4];
#pragma unroll
                for (int mi = 0; mi < 2; mi++) {
                    int r = wm * 32 + mi * 16 + (lane >> 2);
                    int kb = kk + (lane & 3);
                    a[mi][0] = As[r * 36 + kb];
                    a[mi][1] = As[(r + 8) * 36 + kb];
                    a[mi][2] = As[r * 36 + kb + 4];
                    a[mi][3] = As[(r + 8) * 36 + kb + 4];
                }
                uint32_t b[4][2];
#pragma unroll
                for (int ni = 0; ni < 4; ni++) {
                    int n = wn * 32 + ni * 8 + (lane >> 2);
                    b[ni][0] = Bs[n * 36 + kk + (lane & 3)];
                    b[ni][1] = Bs[n * 36 + kk + (lane & 3) + 4];
                }
#pragma unroll
                for (int mi = 0; mi < 2; mi++)
#pragma unroll
                    for (int ni = 0; ni < 4; ni++)
                        mma_tf32(acc[mi][ni], a[mi], b[ni]);
            }
        }

        // epilogue: 2 chunks of 32 cols
#pragma unroll
        for (int c = 0; c < 2; c++) {
            __syncthreads();
            if (wn == c) {
#pragma unroll
                for (int mi = 0; mi < 2; mi++)
#pragma unroll
                    for (int ni = 0; ni < 4; ni++) {
                        int r0 = wm * 32 + mi * 16 + (lane >> 2);
                        int cc = ni * 8 + (lane & 3) * 2;
                        buf[r0 * 33 + cc]           = acc[mi][ni][0];
                        buf[r0 * 33 + cc + 1]       = acc[mi][ni][1];
                        buf[(r0 + 8) * 33 + cc]     = acc[mi][ni][2];
                        buf[(r0 + 8) * 33 + cc + 1] = acc[mi][ni][3];
                    }
            }
            __syncthreads();
#pragma unroll
            for (int it = 0; it < 4; it++) {
                int row = it * 32 + (tid >> 3);
                int c4 = (tid & 7) * 4;
                int col0 = h * 64 + c * 32 + c4;
                float v0 = buf[row * 33 + c4]     + s_b1[col0];
                float v1 = buf[row * 33 + c4 + 1] + s_b1[col0 + 1];
                float v2 = buf[row * 33 + c4 + 2] + s_b1[col0 + 2];
                float v3 = buf[row * 33 + c4 + 3] + s_b1[col0 + 3];
                v0 = v0 > 0.f ? v0 : 0.f;
                v1 = v1 > 0.f ? v1 : 0.f;
                v2 = v2 > 0.f ? v2 : 0.f;
                v3 = v3 > 0.f ? v3 : 0.f;
                float p  = v0 * s_wa2[col0 * 2]     + v1 * s_wa2[(col0 + 1) * 2]
                         + v2 * s_wa2[(col0 + 2) * 2] + v3 * s_wa2[(col0 + 3) * 2];
                float pd = v0 * s_wa2[col0 * 2 + 1]   + v1 * s_wa2[(col0 + 1) * 2 + 1]
                         + v2 * s_wa2[(col0 + 2) * 2 + 1] + v3 * s_wa2[(col0 + 3) * 2 + 1];
#pragma unroll
                for (int o = 1; o < 8; o <<= 1) {
                    p  += __shfl_xor_sync(0xffffffffu, p, o);
                    pd += __shfl_xor_sync(0xffffffffu, pd, o);
                }
                if ((tid & 7) == 0) { s_als[row] += p; s_ald[row] += pd; }
                int m = m0 + row;
                if (m < M)
                    *(float4*)(g_H1A + (size_t)m * D1 + col0) = make_float4(v0, v1, v2, v3);
            }
        }
    }
    __syncthreads();
    if (tid < 128) {
        int m = m0 + tid;
        if (m < M) { g_ALS2[m] = s_als[tid]; g_ALD2[m] = s_ald[tid]; }
    }
}

// ================= GEMM2: H2 = H1A @ W2  (mma.sync tf32) =================
__global__ __launch_bounds__(256)
void g2_mma(int M)
{
    __shared__ uint32_t As[128 * 36];
    __shared__ uint32_t Bs[64 * 36];
    __shared__ float buf[128 * 33];

    int tid = threadIdx.x;
    int wid = tid >> 5, lane = tid & 31;
    int wm = wid >> 1, wn = wid & 1;
    int m0 = blockIdx.x * 128;

    float acc[2][4][4];
#pragma unroll
    for (int i = 0; i < 2; i++)
#pragma unroll
        for (int j = 0; j < 4; j++)
#pragma unroll
            for (int k = 0; k < 4; k++) acc[i][j][k] = 0.f;

    for (int k0 = 0; k0 < D1; k0 += 32) {
#pragma unroll
        for (int it = 0; it < 4; it++) {
            int idx = tid + it * 256;
            int row = idx >> 3, c4 = (idx & 7) * 4;
            int m = m0 + row; if (m >= M) m = M - 1;
            float4 v = *(const float4*)(g_H1A + (size_t)m * D1 + k0 + c4);
            uint32_t* p = As + row * 36 + c4;
            p[0] = f2tf32(v.x); p[1] = f2tf32(v.y); p[2] = f2tf32(v.z); p[3] = f2tf32(v.w);
        }
#pragma unroll
        for (int it = 0; it < 2; it++) {
            int idx = tid + it * 256;
            int row = idx >> 3, c4 = (idx & 7) * 4;
            float4 v = *(const float4*)(g_WT2 + (size_t)row * D1 + k0 + c4);
            uint32_t* p = Bs + row * 36 + c4;
            p[0] = f2tf32(v.x); p[1] = f2tf32(v.y); p[2] = f2tf32(v.z); p[3] = f2tf32(v.w);
        }
        __syncthreads();
#pragma unroll
        for (int kk = 0; kk < 32; kk += 8) {
            uint32_t a[2][4];
#pragma unroll
            for (int mi = 0; mi < 2; mi++) {
                int r = wm * 32 + mi * 16 + (lane >> 2);
                int kb = kk + (lane & 3);
                a[mi][0] = As[r * 36 + kb];
                a[mi][1] = As[(r + 8) * 36 + kb];
                a[mi][2] = As[r * 36 + kb + 4];
                a[mi][3] = As[(r + 8) * 36 + kb + 4];
            }
            uint32_t b[4][2];
#pragma unroll
            for (int ni = 0; ni < 4; ni++) {
                int n = wn * 32 + ni * 8 + (lane >> 2);
                b[ni][0] = Bs[n * 36 + kk + (lane & 3)];
                b[ni][1] = Bs[n * 36 + kk + (lane & 3) + 4];
            }
#pragma unroll
            for (int mi = 0; mi < 2; mi++)
#pragma unroll
                for (int ni = 0; ni < 4; ni++)
                    mma_tf32(acc[mi][ni], a[mi], b[ni]);
        }
        __syncthreads();
    }

#pragma unroll
    for (int c = 0; c < 2; c++) {
        if (wn == c) {
#pragma unroll
            for (int mi = 0; mi < 2; mi++)
#pragma unroll
                for (int ni = 0; ni < 4; ni++) {
                    int r0 = wm * 32 + mi * 16 + (lane >> 2);
                    int cc = ni * 8 + (lane & 3) * 2;
                    buf[r0 * 33 + cc]           = acc[mi][ni][0];
                    buf[r0 * 33 + cc + 1]       = acc[mi][ni][1];
                    buf[(r0 + 8) * 33 + cc]     = acc[mi][ni][2];
                    buf[(r0 + 8) * 33 + cc + 1] = acc[mi][ni][3];
                }
        }
        __syncthreads();
#pragma unroll
        for (int it = 0; it < 4; it++) {
            int row = it * 32 + (tid >> 3);
            int c4 = (tid & 7) * 4;
            int m = m0 + row;
            if (m < M) {
                float4 v = make_float4(buf[row * 33 + c4], buf[row * 33 + c4 + 1],
                                       buf[row * 33 + c4 + 2], buf[row * 33 + c4 + 3]);
                *(float4*)(g_H2 + (size_t)m * HIDC + c * 32 + c4) = v;
            }
        }
        __syncthreads();
    }
}

// ---------------- layer 2: fused stats + aggregate + relu + projection ----------------
__global__ __launch_bounds__(64) void k_gat2(
    const float* __restrict__ b2, const float* __restrict__ Wc,
    const float* __restrict__ bc, float* __restrict__ out, int NN)
{
    __shared__ float s_red[64];
    __shared__ float s_max, s_inv;
    __shared__ float s_alpha[64];
    __shared__ int   s_sidx[64];
    int n = blockIdx.x;
    int t = threadIdx.x;
    float ald = g_ALD2[n];
    int j0 = g_ROFF[n], j1 = g_ROFF[n + 1];

    // pass A: max
    float mx = -1e30f;
    for (int j = j0 + t; j < j1; j += 64)
        mx = fmaxf(mx, lrelu(g_ALS2[g_CSRS[j]] + ald));
    s_red[t] = mx;
    __syncthreads();
#pragma unroll
    for (int off = 32; off; off >>= 1) {
        if (t < off) s_red[t] = fmaxf(s_red[t], s_red[t + off]);
        __syncthreads();
    }
    if (t == 0) s_max = s_red[0];
    __syncthreads();

    // pass B: denom
    float sm = 0.f;
    for (int j = j0 + t; j < j1; j += 64)
        sm += __expf(lrelu(g_ALS2[g_CSRS[j]] + ald) - s_max);
    s_red[t] = sm;
    __syncthreads();
#pragma unroll
    for (int off = 32; off; off >>= 1) {
        if (t < off) s_red[t] += s_red[t + off];
        __syncthreads();
    }
    if (t == 0) s_inv = 1.f / s_red[0];
    __syncthreads();

    // pass C: aggregate
    float acc = 0.f;
    for (int jb = j0; jb < j1; jb += 64) {
        int cnt = j1 - jb; if (cnt > 64) cnt = 64;
        if (t < cnt) {
            int s = g_CSRS[jb + t];
            s_sidx[t] = s;
            s_alpha[t] = __expf(lrelu(g_ALS2[s] + ald) - s_max) * s_inv;
        }
        __syncthreads();
        for (int q = 0; q < cnt; q++)
            acc += s_alpha[q] * g_H2[(size_t)s_sidx[q] * HIDC + t];
        __syncthreads();
    }
    float v = acc + b2[t];
    v = v > 0.f ? v : 0.f;
    v *= Wc[t];
    s_red[t] = v;
    __syncthreads();
#pragma unroll
    for (int off = 32; off; off >>= 1) {
        if (t < off) s_red[t] += s_red[t + off];
        __syncthreads();
    }
    if (t == 0) out[n] = s_red[0] + bc[0];
}

// ---------------- host launcher ----------------
extern "C" void kernel_launch(void* const* d_in, const int* in_sizes, int n_in,
                              void* d_out, int out_size)
{
    const float* x     = (const float*)d_in[0];
    const void*  eidx  = d_in[1];
    const float* W1    = (const float*)d_in[2];
    const float* asrc1 = (const float*)d_in[3];
    const float* adst1 = (const float*)d_in[4];
    const float* b1    = (const float*)d_in[5];
    const float* W2    = (const float*)d_in[6];
    const float* asrc2 = (const float*)d_in[7];
    const float* adst2 = (const float*)d_in[8];
    const float* b2    = (const float*)d_in[9];
    const float* Wc    = (const float*)d_in[10];
    const float* bc    = (const float*)d_in[11];
    float* out = (float*)d_out;

    int NN = in_sizes[0] / FIN;  if (NN > NN_MAX) NN = NN_MAX;
    int E  = in_sizes[1] / 2;    if (E  > E_MAX)  E  = E_MAX;
    int Et = E + NN;
    int MT = (NN + 127) / 128;
    const int TB = 256;

    cudaFuncSetAttribute(k_h1gemm, cudaFuncAttributeMaxDynamicSharedMemorySize, H1_SMEMB);

    float *WT1p, *WT2p;
    cudaGetSymbolAddress((void**)&WT1p, g_WT1);
    cudaGetSymbolAddress((void**)&WT2p, g_WT2);

    // edge decode + CSR
    k_detect<<<1, 256>>>((const int*)eidx, E);
    k_convert<<<(E + TB - 1) / TB, TB>>>(eidx, E);
    k_zero_deg<<<(NN + TB - 1) / TB, TB>>>(NN);
    k_degree<<<(Et + TB - 1) / TB, TB>>>(E, Et);
    k_scan<<<1, 1024>>>(NN);
    k_scatter<<<(Et + TB - 1) / TB, TB>>>(E, Et);

    // weight prep
    {
        dim3 b(32, 8);
        dim3 gt1(D1 / 32, FIN / 32);
        k_transpose<<<gt1, b>>>(W1, WT1p, FIN, D1);
        dim3 gt2(HIDC / 32, D1 / 32);
        k_transpose<<<gt2, b>>>(W2, WT2p, D1, HIDC);
        k_wa<<<FIN * 16 + D1 * 2, 32>>>(W1, asrc1, adst1, W2, asrc2, adst2);
    }

    // layer 1
    k_al1<<<(NN + 7) / 8, 256>>>(x, NN);
    k_gat1<<<NN, 256>>>(x, NN);
    k_h1gemm<<<MT, 256, H1_SMEMB>>>(b1, NN);

    // layer 2
    g2_mma<<<MT, 256>>>(NN);
    k_gat2<<<NN, 64>>>(b2, Wc, bc, out, NN);

    (void)n_in; (void)out_size;
}

// round 8
// speedup vs baseline: 1.5540x; 1.5540x over previous
#include <cuda_runtime.h>
#include <cstdint>

// ---------------- problem constants ----------------
#define NN_MAX 50000
#define E_MAX  400000
#define ET_MAX (E_MAX + NN_MAX)
#define FIN    128
#define D1     512
#define HIDC   64
#define HEADS  8
#define NEG    0.2f

// ---------------- scratch ----------------
__device__ float    g_H1 [NN_MAX * (size_t)D1];
__device__ float    g_H1A[NN_MAX * (size_t)D1];
__device__ float    g_H2 [NN_MAX * (size_t)HIDC];
__device__ float    g_WT1[D1 * FIN];      // W1^T  [512,128]
__device__ float    g_WT2[HIDC * D1];     // W2^T  [64,512]
__device__ float    g_ALS1[NN_MAX * HEADS];
__device__ float    g_ALD1[NN_MAX * HEADS];
__device__ float    g_ALS2[NN_MAX];
__device__ float    g_ALD2[NN_MAX];
__device__ int      g_SRC[E_MAX];
__device__ int      g_DST[E_MAX];
__device__ int      g_DEG[NN_MAX];
__device__ int      g_ROFF[NN_MAX + 1];
__device__ int      g_CUR[NN_MAX];
__device__ int      g_CSRS[ET_MAX];
__device__ int      g_FLAG64;

// ---------------- helpers ----------------
__device__ __forceinline__ float lrelu(float x) { return x > 0.f ? x : NEG * x; }
__device__ __forceinline__ uint32_t f2tf32(float f) {
    uint32_t r;
    asm("cvt.rna.tf32.f32 %0, %1;" : "=r"(r) : "f"(f));
    return r;
}
__device__ __forceinline__ void mma_tf32(float* c, const uint32_t* a, const uint32_t* b) {
    asm volatile("mma.sync.aligned.m16n8k8.row.col.f32.tf32.tf32.f32 "
        "{%0,%1,%2,%3}, {%4,%5,%6,%7}, {%8,%9}, {%0,%1,%2,%3};"
        : "+f"(c[0]), "+f"(c[1]), "+f"(c[2]), "+f"(c[3])
        : "r"(a[0]), "r"(a[1]), "r"(a[2]), "r"(a[3]), "r"(b[0]), "r"(b[1]));
}

// ---------------- edge dtype detection + conversion ----------------
__global__ void k_detect(const int* __restrict__ p, int E) {
    __shared__ int nz;
    if (threadIdx.x == 0) nz = 0;
    __syncthreads();
    int total = 2 * E; if (total > 4096) total = 4096;
    int local = 0;
    for (int i = 2 * (int)threadIdx.x + 1; i < total; i += 2 * (int)blockDim.x)
        local |= p[i];
    if (local) atomicOr(&nz, 1);
    __syncthreads();
    if (threadIdx.x == 0) g_FLAG64 = (nz == 0) ? 1 : 0;
}
__global__ void k_convert(const void* __restrict__ buf, int E) {
    int i = blockIdx.x * blockDim.x + threadIdx.x;
    if (i >= E) return;
    if (g_FLAG64) {
        const long long* p = (const long long*)buf;
        g_SRC[i] = (int)p[i];
        g_DST[i] = (int)p[E + i];
    } else {
        const int* p = (const int*)buf;
        g_SRC[i] = p[i];
        g_DST[i] = p[E + i];
    }
}

// ---------------- CSR build ----------------
__global__ void k_zero_deg(int n) {
    int i = blockIdx.x * blockDim.x + threadIdx.x;
    if (i < n) g_DEG[i] = 0;
}
__global__ void k_degree(int E, int Et) {
    int i = blockIdx.x * blockDim.x + threadIdx.x;
    if (i >= Et) return;
    int d = (i < E) ? g_DST[i] : (i - E);
    atomicAdd(&g_DEG[d], 1);
}
__global__ void k_scan(int NN) {
    __shared__ int sums[1024];
    int t = threadIdx.x;
    int chunk = (NN + 1023) >> 10;
    int beg = t * chunk;
    int end = beg + chunk; if (end > NN) end = NN;
    int s = 0;
    for (int i = beg; i < end; i++) s += g_DEG[i];
    sums[t] = s;
    __syncthreads();
    for (int off = 1; off < 1024; off <<= 1) {
        int v = (t >= off) ? sums[t - off] : 0;
        __syncthreads();
        sums[t] += v;
        __syncthreads();
    }
    int run = (t == 0) ? 0 : sums[t - 1];
    for (int i = beg; i < end; i++) {
        int d = g_DEG[i];
        g_ROFF[i] = run;
        g_CUR[i]  = run;
        run += d;
    }
    if (t == 0) g_ROFF[NN] = sums[1023];
}
__global__ void k_scatter(int E, int Et) {
    int i = blockIdx.x * blockDim.x + threadIdx.x;
    if (i >= Et) return;
    int s, d;
    if (i < E) { s = g_SRC[i]; d = g_DST[i]; }
    else       { s = d = i - E; }
    int pos = atomicAdd(&g_CUR[d], 1);
    g_CSRS[pos] = s;
}

// ---------------- weight transposes ----------------
__global__ void k_transpose(const float* __restrict__ W, float* __restrict__ WT, int K, int N) {
    __shared__ float tile[32][33];
    int n0 = blockIdx.x * 32, k0 = blockIdx.y * 32;
    int tx = threadIdx.x, ty = threadIdx.y;   // 32 x 8
#pragma unroll
    for (int i = 0; i < 32; i += 8)
        tile[ty + i][tx] = W[(size_t)(k0 + ty + i) * N + n0 + tx];
    __syncthreads();
#pragma unroll
    for (int i = 0; i < 32; i += 8)
        WT[(size_t)(n0 + ty + i) * K + k0 + tx] = tile[tx][ty + i];
}

// ================= GEMM1: H1 = x @ W1  (mma.sync tf32) =================
// Block tile M=128, N=128, K=128 (BK=32). 256 threads, 8 warps (4m x 2n),
// warp tile 32x64. Fused ALS1/ALD1 (CTA's 128 cols == heads 2nb..2nb+1).
#define G1_AS   0
#define G1_BS   4608
#define G1_BUF  9216
#define G1_SAS  13440
#define G1_SAD  13568
#define G1_SALS 13696
#define G1_SALD 13952
#define G1_SMEMF 14208
#define G1_SMEMB (G1_SMEMF * 4)

__global__ __launch_bounds__(256)
void g1_mma(const float* __restrict__ A, const float* __restrict__ asrc,
            const float* __restrict__ adst, int M)
{
    extern __shared__ float sm[];
    uint32_t* As = (uint32_t*)(sm + G1_AS);
    uint32_t* Bs = (uint32_t*)(sm + G1_BS);
    float* buf   = sm + G1_BUF;
    float* s_as  = sm + G1_SAS;
    float* s_ad  = sm + G1_SAD;
    float* s_als = sm + G1_SALS;
    float* s_ald = sm + G1_SALD;

    int tid = threadIdx.x;
    int wid = tid >> 5, lane = tid & 31;
    int wm = wid >> 1, wn = wid & 1;
    int nb = blockIdx.x;              // 0..3
    int m0 = blockIdx.y * 128;

    if (tid < 128) {
        s_as[tid] = asrc[nb * 128 + tid];
        s_ad[tid] = adst[nb * 128 + tid];
    }
    s_als[tid] = 0.f;
    s_ald[tid] = 0.f;

    float acc[2][8][4];
#pragma unroll
    for (int i = 0; i < 2; i++)
#pragma unroll
        for (int j = 0; j < 8; j++)
#pragma unroll
            for (int k = 0; k < 4; k++) acc[i][j][k] = 0.f;

    for (int k0 = 0; k0 < FIN; k0 += 32) {
#pragma unroll
        for (int it = 0; it < 4; it++) {
            int idx = tid + it * 256;
            int row = idx >> 3, c4 = (idx & 7) * 4;
            int m = m0 + row; if (m >= M) m = M - 1;
            float4 v = *(const float4*)(A + (size_t)m * FIN + k0 + c4);
            uint32_t* p = As + row * 36 + c4;
            p[0] = f2tf32(v.x); p[1] = f2tf32(v.y); p[2] = f2tf32(v.z); p[3] = f2tf32(v.w);
        }
#pragma unroll
        for (int it = 0; it < 4; it++) {
            int idx = tid + it * 256;
            int row = idx >> 3, c4 = (idx & 7) * 4;
            float4 v = *(const float4*)(g_WT1 + (size_t)(nb * 128 + row) * FIN + k0 + c4);
            uint32_t* p = Bs + row * 36 + c4;
            p[0] = f2tf32(v.x); p[1] = f2tf32(v.y); p[2] = f2tf32(v.z); p[3] = f2tf32(v.w);
        }
        __syncthreads();
#pragma unroll
        for (int kk = 0; kk < 32; kk += 8) {
            uint32_t a[2][4];
#pragma unroll
            for (int mi = 0; mi < 2; mi++) {
                int r = wm * 32 + mi * 16 + (lane >> 2);
                int kb = kk + (lane & 3);
                a[mi][0] = As[r * 36 + kb];
                a[mi][1] = As[(r + 8) * 36 + kb];
                a[mi][2] = As[r * 36 + kb + 4];
                a[mi][3] = As[(r + 8) * 36 + kb + 4];
            }
            uint32_t b[8][2];
#pragma unroll
            for (int ni = 0; ni < 8; ni++) {
                int n = wn * 64 + ni * 8 + (lane >> 2);
                b[ni][0] = Bs[n * 36 + kk + (lane & 3)];
                b[ni][1] = Bs[n * 36 + kk + (lane & 3) + 4];
            }
#pragma unroll
            for (int mi = 0; mi < 2; mi++)
#pragma unroll
                for (int ni = 0; ni < 8; ni++)
                    mma_tf32(acc[mi][ni], a[mi], b[ni]);
        }
        __syncthreads();
    }

    // epilogue: 4 chunks of 32 cols; stage -> coalesced store + fused logits
#pragma unroll
    for (int c = 0; c < 4; c++) {
        if (wn == (c >> 1)) {
#pragma unroll
            for (int mi = 0; mi < 2; mi++)
#pragma unroll
                for (int nl = 0; nl < 4; nl++) {
                    int ni = (c & 1) * 4 + nl;
                    int r0 = wm * 32 + mi * 16 + (lane >> 2);
                    int cc = nl * 8 + (lane & 3) * 2;
                    buf[r0 * 33 + cc]           = acc[mi][ni][0];
                    buf[r0 * 33 + cc + 1]       = acc[mi][ni][1];
                    buf[(r0 + 8) * 33 + cc]     = acc[mi][ni][2];
                    buf[(r0 + 8) * 33 + cc + 1] = acc[mi][ni][3];
                }
        }
        __syncthreads();
        int lh = c >> 1;
#pragma unroll
        for (int it = 0; it < 4; it++) {
            int row = it * 32 + (tid >> 3);
            int c4 = (tid & 7) * 4;
            float vx = buf[row * 33 + c4];
            float vy = buf[row * 33 + c4 + 1];
            float vz = buf[row * 33 + c4 + 2];
            float vw = buf[row * 33 + c4 + 3];
            int cb = c * 32 + c4;
            float p  = vx * s_as[cb] + vy * s_as[cb + 1] + vz * s_as[cb + 2] + vw * s_as[cb + 3];
            float pd = vx * s_ad[cb] + vy * s_ad[cb + 1] + vz * s_ad[cb + 2] + vw * s_ad[cb + 3];
#pragma unroll
            for (int o = 1; o < 8; o <<= 1) {
                p  += __shfl_xor_sync(0xffffffffu, p, o);
                pd += __shfl_xor_sync(0xffffffffu, pd, o);
            }
            if ((tid & 7) == 0) {
                s_als[row * 2 + lh] += p;
                s_ald[row * 2 + lh] += pd;
            }
            int m = m0 + row;
            if (m < M) {
                float4 v = make_float4(vx, vy, vz, vw);
                *(float4*)(g_H1 + (size_t)m * D1 + nb * 128 + cb) = v;
            }
        }
        __syncthreads();
    }
    if (tid < 128) {
        int m = m0 + tid;
        if (m < M) {
            g_ALS1[m * HEADS + nb * 2 + 0] = s_als[tid * 2 + 0];
            g_ALS1[m * HEADS + nb * 2 + 1] = s_als[tid * 2 + 1];
            g_ALD1[m * HEADS + nb * 2 + 0] = s_ald[tid * 2 + 0];
            g_ALD1[m * HEADS + nb * 2 + 1] = s_ald[tid * 2 + 1];
        }
    }
}

// ================= GEMM2: H2 = H1A @ W2  (mma.sync tf32), fused AL2 =================
__global__ __launch_bounds__(256)
void g2_mma(const float* __restrict__ asrc, const float* __restrict__ adst, int M)
{
    __shared__ uint32_t As[128 * 36];
    __shared__ uint32_t Bs[64 * 36];
    __shared__ float buf[128 * 33];
    __shared__ float s_as[64], s_ad[64];
    __shared__ float s_als[128], s_ald[128];

    int tid = threadIdx.x;
    int wid = tid >> 5, lane = tid & 31;
    int wm = wid >> 1, wn = wid & 1;
    int m0 = blockIdx.x * 128;

    if (tid < 64) { s_as[tid] = asrc[tid]; s_ad[tid] = adst[tid]; }
    if (tid < 128) { s_als[tid] = 0.f; s_ald[tid] = 0.f; }

    float acc[2][4][4];
#pragma unroll
    for (int i = 0; i < 2; i++)
#pragma unroll
        for (int j = 0; j < 4; j++)
#pragma unroll
            for (int k = 0; k < 4; k++) acc[i][j][k] = 0.f;

    for (int k0 = 0; k0 < D1; k0 += 32) {
#pragma unroll
        for (int it = 0; it < 4; it++) {
            int idx = tid + it * 256;
            int row = idx >> 3, c4 = (idx & 7) * 4;
            int m = m0 + row; if (m >= M) m = M - 1;
            float4 v = *(const float4*)(g_H1A + (size_t)m * D1 + k0 + c4);
            uint32_t* p = As + row * 36 + c4;
            p[0] = f2tf32(v.x); p[1] = f2tf32(v.y); p[2] = f2tf32(v.z); p[3] = f2tf32(v.w);
        }
#pragma unroll
        for (int it = 0; it < 2; it++) {
            int idx = tid + it * 256;
            int row = idx >> 3, c4 = (idx & 7) * 4;
            float4 v = *(const float4*)(g_WT2 + (size_t)row * D1 + k0 + c4);
            uint32_t* p = Bs + row * 36 + c4;
            p[0] = f2tf32(v.x); p[1] = f2tf32(v.y); p[2] = f2tf32(v.z); p[3] = f2tf32(v.w);
        }
        __syncthreads();
#pragma unroll
        for (int kk = 0; kk < 32; kk += 8) {
            uint32_t a[2][4];
#pragma unroll
            for (int mi = 0; mi < 2; mi++) {
                int r = wm * 32 + mi * 16 + (lane >> 2);
                int kb = kk + (lane & 3);
                a[mi][0] = As[r * 36 + kb];
                a[mi][1] = As[(r + 8) * 36 + kb];
                a[mi][2] = As[r * 36 + kb + 4];
                a[mi][3] = As[(r + 8) * 36 + kb + 4];
            }
            uint32_t b[4][2];
#pragma unroll
            for (int ni = 0; ni < 4; ni++) {
                int n = wn * 32 + ni * 8 + (lane >> 2);
                b[ni][0] = Bs[n * 36 + kk + (lane & 3)];
                b[ni][1] = Bs[n * 36 + kk + (lane & 3) + 4];
            }
#pragma unroll
            for (int mi = 0; mi < 2; mi++)
#pragma unroll
                for (int ni = 0; ni < 4; ni++)
                    mma_tf32(acc[mi][ni], a[mi], b[ni]);
        }
        __syncthreads();
    }

#pragma unroll
    for (int c = 0; c < 2; c++) {
        if (wn == c) {
#pragma unroll
            for (int mi = 0; mi < 2; mi++)
#pragma unroll
                for (int ni = 0; ni < 4; ni++) {
                    int r0 = wm * 32 + mi * 16 + (lane >> 2);
                    int cc = ni * 8 + (lane & 3) * 2;
                    buf[r0 * 33 + cc]           = acc[mi][ni][0];
                    buf[r0 * 33 + cc + 1]       = acc[mi][ni][1];
                    buf[(r0 + 8) * 33 + cc]     = acc[mi][ni][2];
                    buf[(r0 + 8) * 33 + cc + 1] = acc[mi][ni][3];
                }
        }
        __syncthreads();
#pragma unroll
        for (int it = 0; it < 4; it++) {
            int row = it * 32 + (tid >> 3);
            int c4 = (tid & 7) * 4;
            float vx = buf[row * 33 + c4];
            float vy = buf[row * 33 + c4 + 1];
            float vz = buf[row * 33 + c4 + 2];
            float vw = buf[row * 33 + c4 + 3];
            int cb = c * 32 + c4;
            float p  = vx * s_as[cb] + vy * s_as[cb + 1] + vz * s_as[cb + 2] + vw * s_as[cb + 3];
            float pd = vx * s_ad[cb] + vy * s_ad[cb + 1] + vz * s_ad[cb + 2] + vw * s_ad[cb + 3];
#pragma unroll
            for (int o = 1; o < 8; o <<= 1) {
                p  += __shfl_xor_sync(0xffffffffu, p, o);
                pd += __shfl_xor_sync(0xffffffffu, pd, o);
            }
            if ((tid & 7) == 0) { s_als[row] += p; s_ald[row] += pd; }
            int m = m0 + row;
            if (m < M) {
                float4 v = make_float4(vx, vy, vz, vw);
                *(float4*)(g_H2 + (size_t)m * HIDC + cb) = v;
            }
        }
        __syncthreads();
    }
    if (tid < 128) {
        int m = m0 + tid;
        if (m < M) { g_ALS2[m] = s_als[tid]; g_ALD2[m] = s_ald[tid]; }
    }
}

// ---------------- layer 1 aggregation: fused softmax (no max) + gather ----------------
__global__ __launch_bounds__(128) void k_agg1(const float* __restrict__ b1, int NN) {
    __shared__ float s_ald[HEADS];
    __shared__ float s_alpha[16][8];
    __shared__ int   s_src[16];
    __shared__ float s_red[128];
    int n = blockIdx.x;
    int t = threadIdx.x;              // channels 4t..4t+3, agg head = t>>4
    if (t < HEADS) s_ald[t] = g_ALD1[n * HEADS + t];
    __syncthreads();
    int j0 = g_ROFF[n], j1 = g_ROFF[n + 1];
    int h4 = t >> 4;
    int jj = t >> 3, hh = t & 7;
    float4 acc = make_float4(0.f, 0.f, 0.f, 0.f);
    float dloc = 0.f;
    for (int jb = j0; jb < j1; jb += 16) {
        int cnt = j1 - jb; if (cnt > 16) cnt = 16;
        if (jj < cnt) {
            int s = g_CSRS[jb + jj];
            if (hh == 0) s_src[jj] = s;
            float a = __expf(lrelu(g_ALS1[s * HEADS + hh] + s_ald[hh]));
            s_alpha[jj][hh] = a;
            dloc += a;
        }
        __syncthreads();
        int q = 0;
        for (; q + 4 <= cnt; q += 4) {
            float a0 = s_alpha[q][h4],     a1 = s_alpha[q + 1][h4];
            float a2 = s_alpha[q + 2][h4], a3 = s_alpha[q + 3][h4];
            float4 v0 = *(const float4*)(g_H1 + (size_t)s_src[q]     * D1 + 4 * t);
            float4 v1 = *(const float4*)(g_H1 + (size_t)s_src[q + 1] * D1 + 4 * t);
            float4 v2 = *(const float4*)(g_H1 + (size_t)s_src[q + 2] * D1 + 4 * t);
            float4 v3 = *(const float4*)(g_H1 + (size_t)s_src[q + 3] * D1 + 4 * t);
            acc.x += a0 * v0.x + a1 * v1.x + a2 * v2.x + a3 * v3.x;
            acc.y += a0 * v0.y + a1 * v1.y + a2 * v2.y + a3 * v3.y;
            acc.z += a0 * v0.z + a1 * v1.z + a2 * v2.z + a3 * v3.z;
            acc.w += a0 * v0.w + a1 * v1.w + a2 * v2.w + a3 * v3.w;
        }
        for (; q < cnt; q++) {
            float a = s_alpha[q][h4];
            float4 v = *(const float4*)(g_H1 + (size_t)s_src[q] * D1 + 4 * t);
            acc.x += a * v.x; acc.y += a * v.y; acc.z += a * v.z; acc.w += a * v.w;
        }
        __syncthreads();
    }
    // per-head denom: reduce dloc over jj (t = jj*8+hh)
    s_red[t] = dloc;
    __syncthreads();
#pragma unroll
    for (int off = 64; off >= 8; off >>= 1) {
        if (t < off) s_red[t] += s_red[t + off];
        __syncthreads();
    }
    float inv = 1.f / s_red[h4];
    float4 bv = ((const float4*)b1)[t];
    acc.x = acc.x * inv + bv.x;
    acc.y = acc.y * inv + bv.y;
    acc.z = acc.z * inv + bv.z;
    acc.w = acc.w * inv + bv.w;
    acc.x = acc.x > 0.f ? acc.x : 0.f;
    acc.y = acc.y > 0.f ? acc.y : 0.f;
    acc.z = acc.z > 0.f ? acc.z : 0.f;
    acc.w = acc.w > 0.f ? acc.w : 0.f;
    *(float4*)(g_H1A + (size_t)n * D1 + 4 * t) = acc;
}

// ---------------- layer 2 aggregation: fused softmax + relu + projection ----------------
__global__ __launch_bounds__(64) void k_agg2(
    const float* __restrict__ b2, const float* __restrict__ Wc,
    const float* __restrict__ bc, float* __restrict__ out, int NN)
{
    __shared__ float s_alpha[64];
    __shared__ int   s_sidx[64];
    __shared__ float s_red[64];
    int n = blockIdx.x;
    int t = threadIdx.x;
    float ald = g_ALD2[n];
    int j0 = g_ROFF[n], j1 = g_ROFF[n + 1];
    float acc = 0.f, dloc = 0.f;
    for (int jb = j0; jb < j1; jb += 64) {
        int cnt = j1 - jb; if (cnt > 64) cnt = 64;
        if (t < cnt) {
            int s = g_CSRS[jb + t];
            s_sidx[t] = s;
            float a = __expf(lrelu(g_ALS2[s] + ald));
            s_alpha[t] = a;
            dloc += a;
        }
        __syncthreads();
        int q = 0;
        for (; q + 4 <= cnt; q += 4) {
            float a0 = s_alpha[q], a1 = s_alpha[q + 1], a2 = s_alpha[q + 2], a3 = s_alpha[q + 3];
            float v0 = g_H2[(size_t)s_sidx[q]     * HIDC + t];
            float v1 = g_H2[(size_t)s_sidx[q + 1] * HIDC + t];
            float v2 = g_H2[(size_t)s_sidx[q + 2] * HIDC + t];
            float v3 = g_H2[(size_t)s_sidx[q + 3] * HIDC + t];
            acc += a0 * v0 + a1 * v1 + a2 * v2 + a3 * v3;
        }
        for (; q < cnt; q++)
            acc += s_alpha[q] * g_H2[(size_t)s_sidx[q] * HIDC + t];
        __syncthreads();
    }
    // denom reduce
    s_red[t] = dloc;
    __syncthreads();
#pragma unroll
    for (int off = 32; off; off >>= 1) {
        if (t < off) s_red[t] += s_red[t + off];
        __syncthreads();
    }
    float inv = 1.f / s_red[0];
    __syncthreads();
    float v = acc * inv + b2[t];
    v = v > 0.f ? v : 0.f;
    v *= Wc[t];
    s_red[t] = v;
    __syncthreads();
#pragma unroll
    for (int off = 32; off; off >>= 1) {
        if (t < off) s_red[t] += s_red[t + off];
        __syncthreads();
    }
    if (t == 0) out[n] = s_red[0] + bc[0];
}

// ---------------- host launcher ----------------
extern "C" void kernel_launch(void* const* d_in, const int* in_sizes, int n_in,
                              void* d_out, int out_size)
{
    const float* x     = (const float*)d_in[0];
    const void*  eidx  = d_in[1];
    const float* W1    = (const float*)d_in[2];
    const float* asrc1 = (const float*)d_in[3];
    const float* adst1 = (const float*)d_in[4];
    const float* b1    = (const float*)d_in[5];
    const float* W2    = (const float*)d_in[6];
    const float* asrc2 = (const float*)d_in[7];
    const float* adst2 = (const float*)d_in[8];
    const float* b2    = (const float*)d_in[9];
    const float* Wc    = (const float*)d_in[10];
    const float* bc    = (const float*)d_in[11];
    float* out = (float*)d_out;

    int NN = in_sizes[0] / FIN;  if (NN > NN_MAX) NN = NN_MAX;
    int E  = in_sizes[1] / 2;    if (E  > E_MAX)  E  = E_MAX;
    int Et = E + NN;
    int MT = (NN + 127) / 128;
    const int TB = 256;

    cudaFuncSetAttribute(g1_mma, cudaFuncAttributeMaxDynamicSharedMemorySize, G1_SMEMB);

    float *WT1p, *WT2p;
    cudaGetSymbolAddress((void**)&WT1p, g_WT1);
    cudaGetSymbolAddress((void**)&WT2p, g_WT2);

    // edge decode + CSR
    k_detect<<<1, 256>>>((const int*)eidx, E);
    k_convert<<<(E + TB - 1) / TB, TB>>>(eidx, E);
    k_zero_deg<<<(NN + TB - 1) / TB, TB>>>(NN);
    k_degree<<<(Et + TB - 1) / TB, TB>>>(E, Et);
    k_scan<<<1, 1024>>>(NN);
    k_scatter<<<(Et + TB - 1) / TB, TB>>>(E, Et);

    // weight transposes
    {
        dim3 b(32, 8);
        dim3 gt1(D1 / 32, FIN / 32);
        k_transpose<<<gt1, b>>>(W1, WT1p, FIN, D1);
        dim3 gt2(HIDC / 32, D1 / 32);
        k_transpose<<<gt2, b>>>(W2, WT2p, D1, HIDC);
    }

    // layer 1
    {
        dim3 g1(4, MT);
        g1_mma<<<g1, 256, G1_SMEMB>>>(x, asrc1, adst1, NN);
    }
    k_agg1<<<NN, 128>>>(b1, NN);

    // layer 2
    g2_mma<<<MT, 256>>>(asrc2, adst2, NN);
    k_agg2<<<NN, 64>>>(b2, Wc, bc, out, NN);

    (void)n_in; (void)out_size;
}